// round 3
// baseline (speedup 1.0000x reference)
#include <cuda_runtime.h>
#include <math.h>

#define BB   128          // batch
#define TT   256          // time steps
#define IN   512          // input size
#define HH   1024         // hidden size
#define OUT  512          // output size
#define INH  1536         // IN + HH

// ---------------- scratch (static device memory; ~129.5 MB total) ------------
__device__ float g_h[BB * HH];                    // current hidden state
__device__ float g_c[BB * HH];                    // current cell state
__device__ float g_hs[(size_t)BB * TT * HH];      // [b][t][j] all hidden states

// ---------------- zero h, c --------------------------------------------------
__global__ void zero_hc_kernel() {
    int i = blockIdx.x * blockDim.x + threadIdx.x;
    if (i < BB * HH) { g_h[i] = 0.f; g_c[i] = 0.f; }
}

__device__ __forceinline__ float sigm(float v) {
    return 1.f / (1.f + expf(-v));
}

// ---------------- fused per-timestep kernel ---------------------------------
// One block per 8 hidden units (j0..j0+7). Block computes, for ALL 128 batch
// rows, the 32 gate pre-activations (4 gates x 8 j) via a 128x32x1536 GEMM on
// the concatenated [x_t, h] input, then performs the LSTM cell update for its
// (b, j) range. Grid = 128 blocks, 256 threads.
__global__ void __launch_bounds__(256) k_step(
        int t,
        const float* __restrict__ x,
        const float* __restrict__ Wf, const float* __restrict__ Wi,
        const float* __restrict__ Wc, const float* __restrict__ Wo,
        const float* __restrict__ bf, const float* __restrict__ bi,
        const float* __restrict__ bc, const float* __restrict__ bo)
{
    __shared__ float As[32][128];    // [k][row]  combined-input tile
    __shared__ float Bs[32][32];     // [k][col]  weight tile (col = g*8 + jj)
    __shared__ float gbuf[128][32];  // gate pre-activations (post-GEMM)

    const int tid = threadIdx.x;
    const int j0  = blockIdx.x * 8;

    // B-load mapping: each thread loads one float4 of weights per chunk
    const int bc_  = tid >> 3;              // col 0..31
    const int bkq  = (tid & 7) * 4;         // k quad within chunk
    const int bg   = bc_ >> 3;              // gate id
    const float* Wsel = (bg == 0) ? Wf : (bg == 1) ? Wi : (bg == 2) ? Wc : Wo;
    const float* Wrow = Wsel + (size_t)(j0 + (bc_ & 7)) * INH;

    // compute mapping: 4x4 microtile
    const int r0 = (tid >> 3) * 4;          // row group (0,4,...,124)
    const int c0 = (tid & 7) * 4;           // col group (0,4,...,28)

    float acc[4][4];
    #pragma unroll
    for (int i = 0; i < 4; i++)
        #pragma unroll
        for (int c = 0; c < 4; c++) acc[i][c] = 0.f;

    for (int k0 = 0; k0 < INH; k0 += 32) {
        // ---- load A tile: rows = batch, cols = k-chunk of [x_t, h] ----
        float4 av[4];
        #pragma unroll
        for (int p = 0; p < 4; p++) {
            const int idx = tid + p * 256;
            const int row = idx >> 3;
            const int kq  = (idx & 7) * 4;
            const int kk  = k0 + kq;
            if (k0 < IN)
                av[p] = *(const float4*)(x + ((size_t)row * TT + t) * IN + kk);
            else
                av[p] = *(const float4*)(g_h + (size_t)row * HH + (kk - IN));
        }
        // ---- load B tile ----
        const float4 bv = *(const float4*)(Wrow + k0 + bkq);

        __syncthreads();
        #pragma unroll
        for (int p = 0; p < 4; p++) {
            const int idx = tid + p * 256;
            const int row = idx >> 3;
            const int kq  = (idx & 7) * 4;
            As[kq + 0][row] = av[p].x; As[kq + 1][row] = av[p].y;
            As[kq + 2][row] = av[p].z; As[kq + 3][row] = av[p].w;
        }
        Bs[bkq + 0][bc_] = bv.x; Bs[bkq + 1][bc_] = bv.y;
        Bs[bkq + 2][bc_] = bv.z; Bs[bkq + 3][bc_] = bv.w;
        __syncthreads();

        #pragma unroll
        for (int k = 0; k < 32; k++) {
            const float4 a4 = *(const float4*)&As[k][r0];
            const float4 b4 = *(const float4*)&Bs[k][c0];
            const float ar[4] = {a4.x, a4.y, a4.z, a4.w};
            const float br[4] = {b4.x, b4.y, b4.z, b4.w};
            #pragma unroll
            for (int i = 0; i < 4; i++)
                #pragma unroll
                for (int c = 0; c < 4; c++) acc[i][c] += ar[i] * br[c];
        }
    }

    // ---- stage gate tile through smem ----
    #pragma unroll
    for (int i = 0; i < 4; i++)
        #pragma unroll
        for (int c = 0; c < 4; c++) gbuf[r0 + i][c0 + c] = acc[i][c];
    __syncthreads();

    // ---- LSTM cell update: 1024 cells, 4 per thread ----
    #pragma unroll
    for (int p = 0; p < 4; p++) {
        const int cell = tid + p * 256;
        const int b_  = cell >> 3;
        const int jj  = cell & 7;
        const int j   = j0 + jj;

        const float fp = gbuf[b_][      jj] + bf[j];
        const float ip = gbuf[b_][ 8 + jj] + bi[j];
        const float cp = gbuf[b_][16 + jj] + bc[j];
        const float op = gbuf[b_][24 + jj] + bo[j];

        const int idx = b_ * HH + j;
        const float cn = sigm(fp) * g_c[idx] + sigm(ip) * tanhf(cp);
        g_c[idx] = cn;
        const float hn = sigm(op) * tanhf(cn);
        g_h[idx] = hn;
        g_hs[((size_t)b_ * TT + t) * HH + j] = hn;
    }
}

// ---------------- kernel 3: out = hs @ W_out^T + b_out -----------------------
// tile 128x128, 256 threads, 8x8 microkernel, K-chunk 8. K = HH = 1024.
__global__ void __launch_bounds__(256, 2) k3_out(
                       const float* __restrict__ Wout,
                       const float* __restrict__ bout,
                       float* __restrict__ out)
{
    __shared__ float As[8][128];
    __shared__ float Bs[8][128];

    const int m0 = blockIdx.x * 128;
    const int n0 = blockIdx.y * 128;
    const int tid = threadIdx.x;
    const int lr = tid >> 1;
    const int lk = (tid & 1) * 4;

    const float* Arow = g_hs + (size_t)(m0 + lr) * HH;
    const float* Brow = Wout + (size_t)(n0 + lr) * HH;

    float acc[8][8];
    #pragma unroll
    for (int i = 0; i < 8; i++)
        #pragma unroll
        for (int j = 0; j < 8; j++) acc[i][j] = 0.f;

    const int r0 = (tid >> 4) * 8;
    const int c0 = (tid & 15) * 8;

    for (int k0 = 0; k0 < HH; k0 += 8) {
        float4 av = *(const float4*)(Arow + k0 + lk);
        float4 bv = *(const float4*)(Brow + k0 + lk);
        __syncthreads();
        As[lk + 0][lr] = av.x; As[lk + 1][lr] = av.y; As[lk + 2][lr] = av.z; As[lk + 3][lr] = av.w;
        Bs[lk + 0][lr] = bv.x; Bs[lk + 1][lr] = bv.y; Bs[lk + 2][lr] = bv.z; Bs[lk + 3][lr] = bv.w;
        __syncthreads();
        #pragma unroll
        for (int k = 0; k < 8; k++) {
            float4 a0 = *(const float4*)&As[k][r0];
            float4 a1 = *(const float4*)&As[k][r0 + 4];
            float4 b0 = *(const float4*)&Bs[k][c0];
            float4 b1 = *(const float4*)&Bs[k][c0 + 4];
            float ar[8] = {a0.x, a0.y, a0.z, a0.w, a1.x, a1.y, a1.z, a1.w};
            float br[8] = {b0.x, b0.y, b0.z, b0.w, b1.x, b1.y, b1.z, b1.w};
            #pragma unroll
            for (int i = 0; i < 8; i++)
                #pragma unroll
                for (int j = 0; j < 8; j++) acc[i][j] += ar[i] * br[j];
        }
    }

    #pragma unroll
    for (int i = 0; i < 8; i++) {
        float* Crow = out + (size_t)(m0 + r0 + i) * OUT + n0;
        #pragma unroll
        for (int j = 0; j < 8; j++) Crow[c0 + j] = acc[i][j] + bout[n0 + c0 + j];
    }
}

// ---------------- launch -----------------------------------------------------
extern "C" void kernel_launch(void* const* d_in, const int* in_sizes, int n_in,
                              void* d_out, int out_size)
{
    const float* x    = (const float*)d_in[0];
    const float* Wf   = (const float*)d_in[1];
    const float* bf   = (const float*)d_in[2];
    const float* Wi   = (const float*)d_in[3];
    const float* bi   = (const float*)d_in[4];
    const float* Wc   = (const float*)d_in[5];
    const float* bc   = (const float*)d_in[6];
    const float* Wo   = (const float*)d_in[7];
    const float* bo   = (const float*)d_in[8];
    const float* Wout = (const float*)d_in[9];
    const float* bout = (const float*)d_in[10];
    float* out = (float*)d_out;

    zero_hc_kernel<<<(BB * HH + 255) / 256, 256>>>();

    // sequential recurrence: one fused kernel per timestep
    for (int t = 0; t < TT; t++) {
        k_step<<<HH / 8, 256>>>(t, x, Wf, Wi, Wc, Wo, bf, bi, bc, bo);
    }

    // output projection (parallel)
    k3_out<<<dim3((BB * TT) / 128, OUT / 128), 256>>>(Wout, bout, out);
}

// round 6
// speedup vs baseline: 1.4992x; 1.4992x over previous
#include <cuda_runtime.h>
#include <cuda_bf16.h>
#include <math.h>
#include <stdint.h>

#define BB   128
#define TT   256
#define IN   512
#define HH   1024
#define OUT  512
#define NG   4096
#define INH  1536
#define KC   64
#define SPAD 72      // smem row stride in bf16 (64 + 8 pad)

// ---------------- static device scratch (~160 MB) -----------------------------
__device__ __nv_bfloat16 g_Wrhi[(size_t)NG * INH];   // reordered: r = bx*32 + gate*8 + jl
__device__ __nv_bfloat16 g_Wrlo[(size_t)NG * INH];
__device__ float         g_biasr[NG];
__device__ float         g_c[BB * HH];
__device__ __nv_bfloat16 g_hshi[(size_t)BB * TT * HH];   // [b][t][j]
__device__ __nv_bfloat16 g_hslo[(size_t)BB * TT * HH];

__device__ __forceinline__ float sigm(float v) { return 1.f / (1.f + expf(-v)); }

__device__ __forceinline__ void mma_bf16(float* c, const uint32_t* a, const uint32_t* b) {
    asm volatile(
        "mma.sync.aligned.m16n8k16.row.col.f32.bf16.bf16.f32 "
        "{%0,%1,%2,%3}, {%4,%5,%6,%7}, {%8,%9}, {%0,%1,%2,%3};"
        : "+f"(c[0]), "+f"(c[1]), "+f"(c[2]), "+f"(c[3])
        : "r"(a[0]), "r"(a[1]), "r"(a[2]), "r"(a[3]), "r"(b[0]), "r"(b[1]));
}

// pack 8 fp32 -> hi uint4 (8 bf16) + lo uint4
__device__ __forceinline__ void split8(const float4 f0, const float4 f1,
                                       uint4& hi, uint4& lo)
{
    const float v[8] = {f0.x, f0.y, f0.z, f0.w, f1.x, f1.y, f1.z, f1.w};
    __nv_bfloat16 h[8], l[8];
    #pragma unroll
    for (int i = 0; i < 8; i++) {
        h[i] = __float2bfloat16(v[i]);
        l[i] = __float2bfloat16(v[i] - __bfloat162float(h[i]));
    }
    hi = *(const uint4*)h;
    lo = *(const uint4*)l;
}

// ---------------- conversion kernels -----------------------------------------
__global__ void conv_w(const float* __restrict__ Wf, const float* __restrict__ Wi,
                       const float* __restrict__ Wc, const float* __restrict__ Wo)
{
    size_t idx = (size_t)blockIdx.x * 256 + threadIdx.x;   // over NG*INH
    int r = (int)(idx / INH);
    int k = (int)(idx - (size_t)r * INH);
    int bx   = r >> 5;
    int gate = (r >> 3) & 3;
    int jl   = r & 7;
    int j    = bx * 8 + jl;
    const float* W = (gate == 0) ? Wf : (gate == 1) ? Wi : (gate == 2) ? Wc : Wo;
    float v = W[(size_t)j * INH + k];
    __nv_bfloat16 hi = __float2bfloat16(v);
    g_Wrhi[idx] = hi;
    g_Wrlo[idx] = __float2bfloat16(v - __bfloat162float(hi));
}

__global__ void conv_bias(const float* __restrict__ bf, const float* __restrict__ bi,
                          const float* __restrict__ bc, const float* __restrict__ bo)
{
    int r = blockIdx.x * 256 + threadIdx.x;
    if (r < NG) {
        int bx = r >> 5, gate = (r >> 3) & 3, jl = r & 7;
        int j = bx * 8 + jl;
        const float* b = (gate == 0) ? bf : (gate == 1) ? bi : (gate == 2) ? bc : bo;
        g_biasr[r] = b[j];
    }
}

__global__ void zero_c() {
    int i = blockIdx.x * 256 + threadIdx.x;
    if (i < BB * HH) g_c[i] = 0.f;
}

// ---------------- fused per-timestep kernel (mma.sync bf16 split) ------------
// grid = 128 blocks x 128 threads. Block bx: all 128 batch rows x 32 gate cols
// (c = gate*8 + jl; j = bx*8 + jl). Warp w: rows [32w, 32w+32), all 32 cols.
// K loop over [x_t | h_{t-1}] in chunks of 64 (24 chunks; 8 when t==0).
__global__ void __launch_bounds__(128) k_step(int t, const float* __restrict__ x)
{
    __shared__ __nv_bfloat16 Ah[128][SPAD], Al[128][SPAD];
    __shared__ __nv_bfloat16 Bh[32][SPAD],  Bl[32][SPAD];
    __shared__ float bias_s[32];

    const int tid  = threadIdx.x;
    const int w    = tid >> 5;
    const int lane = tid & 31;
    const int g    = lane >> 2;
    const int t2   = lane & 3;
    const int n0   = blockIdx.x * 32;
    const int j0   = blockIdx.x * 8;

    if (tid < 32) bias_s[tid] = g_biasr[n0 + tid];

    float acc[2][4][4];
    #pragma unroll
    for (int mt = 0; mt < 2; mt++)
        #pragma unroll
        for (int nt = 0; nt < 4; nt++)
            #pragma unroll
            for (int i = 0; i < 4; i++) acc[mt][nt][i] = 0.f;

    const int nch = (t == 0) ? (IN / KC) : (INH / KC);

    // B staging map: row = tid>>2 (0..31), two uint4 at q = (tid&3)*2, +1
    const int brow = tid >> 2;
    const int bq   = (tid & 3) * 2;

    for (int c_ = 0; c_ < nch; c_++) {
        const int k0 = c_ * KC;

        // ---- gmem loads (A: one 64-elem row-slice per thread; B: 2 uint4) ----
        uint4 avh[8], avl[8];
        if (k0 < IN) {
            // fp32 x, split in registers
            const float* xp = x + ((size_t)tid * TT + t) * IN + k0;
            #pragma unroll
            for (int q = 0; q < 8; q++) {
                const float4 f0 = *(const float4*)(xp + q * 8);
                const float4 f1 = *(const float4*)(xp + q * 8 + 4);
                split8(f0, f1, avh[q], avl[q]);
            }
        } else {
            const size_t abase = ((size_t)tid * TT + (t - 1)) * HH + (k0 - IN);
            #pragma unroll
            for (int q = 0; q < 8; q++) {
                avh[q] = *(const uint4*)(g_hshi + abase + q * 8);
                avl[q] = *(const uint4*)(g_hslo + abase + q * 8);
            }
        }
        const size_t bbase = (size_t)(n0 + brow) * INH + k0;
        uint4 bvh0 = *(const uint4*)(g_Wrhi + bbase + bq * 8);
        uint4 bvh1 = *(const uint4*)(g_Wrhi + bbase + bq * 8 + 8);
        uint4 bvl0 = *(const uint4*)(g_Wrlo + bbase + bq * 8);
        uint4 bvl1 = *(const uint4*)(g_Wrlo + bbase + bq * 8 + 8);

        __syncthreads();   // previous chunk's frag reads done
        #pragma unroll
        for (int q = 0; q < 8; q++) {
            *(uint4*)&Ah[tid][q * 8] = avh[q];
            *(uint4*)&Al[tid][q * 8] = avl[q];
        }
        *(uint4*)&Bh[brow][bq * 8]       = bvh0;
        *(uint4*)&Bh[brow][(bq + 1) * 8] = bvh1;
        *(uint4*)&Bl[brow][bq * 8]       = bvl0;
        *(uint4*)&Bl[brow][(bq + 1) * 8] = bvl1;
        __syncthreads();

        // ---- fragments + mma ----
        #pragma unroll
        for (int ks = 0; ks < 4; ks++) {
            const int kb = ks * 16 + 2 * t2;
            uint32_t ah[2][4], al[2][4];
            #pragma unroll
            for (int mt = 0; mt < 2; mt++) {
                const int r = w * 32 + mt * 16;
                ah[mt][0] = *(const uint32_t*)&Ah[r + g][kb];
                ah[mt][1] = *(const uint32_t*)&Ah[r + g + 8][kb];
                ah[mt][2] = *(const uint32_t*)&Ah[r + g][kb + 8];
                ah[mt][3] = *(const uint32_t*)&Ah[r + g + 8][kb + 8];
                al[mt][0] = *(const uint32_t*)&Al[r + g][kb];
                al[mt][1] = *(const uint32_t*)&Al[r + g + 8][kb];
                al[mt][2] = *(const uint32_t*)&Al[r + g][kb + 8];
                al[mt][3] = *(const uint32_t*)&Al[r + g + 8][kb + 8];
            }
            #pragma unroll
            for (int nt = 0; nt < 4; nt++) {
                uint32_t bh[2], bl[2];
                bh[0] = *(const uint32_t*)&Bh[nt * 8 + g][kb];
                bh[1] = *(const uint32_t*)&Bh[nt * 8 + g][kb + 8];
                bl[0] = *(const uint32_t*)&Bl[nt * 8 + g][kb];
                bl[1] = *(const uint32_t*)&Bl[nt * 8 + g][kb + 8];
                #pragma unroll
                for (int mt = 0; mt < 2; mt++) {
                    mma_bf16(acc[mt][nt], ah[mt], bh);
                    mma_bf16(acc[mt][nt], ah[mt], bl);
                    mma_bf16(acc[mt][nt], al[mt], bh);
                }
            }
        }
    }

    // ---- fused LSTM cell epilogue (pure registers + bias smem) ----
    #pragma unroll
    for (int mt = 0; mt < 2; mt++) {
        #pragma unroll
        for (int dr = 0; dr < 2; dr++) {           // row offset 0 / +8
            const int b_  = w * 32 + mt * 16 + g + dr * 8;
            const int ci0 = dr * 2;                 // c-regs: {ci0, ci0+1} = cols 2t2, 2t2+1
            const int jlA = 2 * t2;

            float hn2[2];
            #pragma unroll
            for (int dc = 0; dc < 2; dc++) {
                const int jl = jlA + dc;
                const int ci = ci0 + dc;
                const float fp = acc[mt][0][ci] + bias_s[jl];
                const float ip = acc[mt][1][ci] + bias_s[8 + jl];
                const float cp = acc[mt][2][ci] + bias_s[16 + jl];
                const float op = acc[mt][3][ci] + bias_s[24 + jl];
                const int  cidx = b_ * HH + j0 + jl;
                const float cn = sigm(fp) * g_c[cidx] + sigm(ip) * tanhf(cp);
                g_c[cidx] = cn;
                hn2[dc] = sigm(op) * tanhf(cn);
            }
            // pack two adjacent j's into one 32-bit store (hi and lo planes)
            const size_t ho = ((size_t)b_ * TT + t) * HH + j0 + jlA;
            __nv_bfloat16 h0 = __float2bfloat16(hn2[0]);
            __nv_bfloat16 h1 = __float2bfloat16(hn2[1]);
            __nv_bfloat162 hhi; hhi.x = h0; hhi.y = h1;
            __nv_bfloat162 hlo;
            hlo.x = __float2bfloat16(hn2[0] - __bfloat162float(h0));
            hlo.y = __float2bfloat16(hn2[1] - __bfloat162float(h1));
            *(__nv_bfloat162*)(g_hshi + ho) = hhi;
            *(__nv_bfloat162*)(g_hslo + ho) = hlo;
        }
    }
}

// ---------------- kernel 3: out = hs @ W_out^T + b_out (fp32 SIMT) -----------
__global__ void __launch_bounds__(256, 2) k3_out(
                       const float* __restrict__ Wout,
                       const float* __restrict__ bout,
                       float* __restrict__ out)
{
    __shared__ float As[8][128];
    __shared__ float Bs[8][128];

    const int m0 = blockIdx.x * 128;
    const int n0 = blockIdx.y * 128;
    const int tid = threadIdx.x;
    const int lr = tid >> 1;
    const int lk = (tid & 1) * 4;

    const __nv_bfloat16* Ahp = g_hshi + (size_t)(m0 + lr) * HH;
    const __nv_bfloat16* Alp = g_hslo + (size_t)(m0 + lr) * HH;
    const float* Brow = Wout + (size_t)(n0 + lr) * HH;

    float acc[8][8];
    #pragma unroll
    for (int i = 0; i < 8; i++)
        #pragma unroll
        for (int j = 0; j < 8; j++) acc[i][j] = 0.f;

    const int r0 = (tid >> 4) * 8;
    const int c0 = (tid & 15) * 8;

    for (int k0 = 0; k0 < HH; k0 += 8) {
        const uint2 rh = *(const uint2*)(Ahp + k0 + lk);
        const uint2 rl = *(const uint2*)(Alp + k0 + lk);
        const __nv_bfloat162 h01 = *(const __nv_bfloat162*)&rh.x;
        const __nv_bfloat162 h23 = *(const __nv_bfloat162*)&rh.y;
        const __nv_bfloat162 l01 = *(const __nv_bfloat162*)&rl.x;
        const __nv_bfloat162 l23 = *(const __nv_bfloat162*)&rl.y;
        float4 av;
        av.x = __bfloat162float(h01.x) + __bfloat162float(l01.x);
        av.y = __bfloat162float(h01.y) + __bfloat162float(l01.y);
        av.z = __bfloat162float(h23.x) + __bfloat162float(l23.x);
        av.w = __bfloat162float(h23.y) + __bfloat162float(l23.y);
        const float4 bv = *(const float4*)(Brow + k0 + lk);
        __syncthreads();
        As[lk + 0][lr] = av.x; As[lk + 1][lr] = av.y; As[lk + 2][lr] = av.z; As[lk + 3][lr] = av.w;
        Bs[lk + 0][lr] = bv.x; Bs[lk + 1][lr] = bv.y; Bs[lk + 2][lr] = bv.z; Bs[lk + 3][lr] = bv.w;
        __syncthreads();
        #pragma unroll
        for (int k = 0; k < 8; k++) {
            float4 a0 = *(const float4*)&As[k][r0];
            float4 a1 = *(const float4*)&As[k][r0 + 4];
            float4 b0 = *(const float4*)&Bs[k][c0];
            float4 b1 = *(const float4*)&Bs[k][c0 + 4];
            float ar[8] = {a0.x, a0.y, a0.z, a0.w, a1.x, a1.y, a1.z, a1.w};
            float br[8] = {b0.x, b0.y, b0.z, b0.w, b1.x, b1.y, b1.z, b1.w};
            #pragma unroll
            for (int i = 0; i < 8; i++)
                #pragma unroll
                for (int j = 0; j < 8; j++) acc[i][j] += ar[i] * br[j];
        }
    }

    #pragma unroll
    for (int i = 0; i < 8; i++) {
        float* Crow = out + (size_t)(m0 + r0 + i) * OUT + n0;
        #pragma unroll
        for (int j = 0; j < 8; j++) Crow[c0 + j] = acc[i][j] + bout[n0 + c0 + j];
    }
}

// ---------------- launch -----------------------------------------------------
extern "C" void kernel_launch(void* const* d_in, const int* in_sizes, int n_in,
                              void* d_out, int out_size)
{
    const float* x    = (const float*)d_in[0];
    const float* Wf   = (const float*)d_in[1];
    const float* bf   = (const float*)d_in[2];
    const float* Wi   = (const float*)d_in[3];
    const float* bi   = (const float*)d_in[4];
    const float* Wc   = (const float*)d_in[5];
    const float* bc   = (const float*)d_in[6];
    const float* Wo   = (const float*)d_in[7];
    const float* bo   = (const float*)d_in[8];
    const float* Wout = (const float*)d_in[9];
    const float* bout = (const float*)d_in[10];
    float* out = (float*)d_out;

    conv_w   <<<(NG * INH) / 256, 256>>>(Wf, Wi, Wc, Wo);
    conv_bias<<<16, 256>>>(bf, bi, bc, bo);
    zero_c   <<<(BB * HH + 255) / 256, 256>>>();

    for (int t = 0; t < TT; t++)
        k_step<<<128, 128>>>(t, x);

    k3_out<<<dim3((BB * TT) / 128, OUT / 128), 256>>>(Wout, bout, out);
}